// round 4
// baseline (speedup 1.0000x reference)
#include <cuda_runtime.h>
#include <cuda_fp16.h>
#include <cstdint>

// ===================== device scratch (no allocs allowed) =====================
__device__ float  g_t12[64 * 64 * 64];          // [o12][i12][r3]
__device__ float  g_t34[64 * 64 * 64];          // [r3][o34][i34]
__device__ __half g_W[4096ull * 4096ull];       // [n][k] fp16
__device__ __half g_X[16384ull * 4096ull];      // [m][k] fp16

// ===================== helpers =====================
__device__ __forceinline__ uint32_t smem_u32(const void* p) {
    uint32_t a;
    asm("{ .reg .u64 t; cvta.to.shared.u64 t, %1; cvt.u32.u64 %0, t; }" : "=r"(a) : "l"(p));
    return a;
}
__device__ __forceinline__ void cp16(uint32_t s, const void* g) {
    asm volatile("cp.async.cg.shared.global [%0], [%1], 16;" :: "r"(s), "l"(g));
}
#define CP_COMMIT() asm volatile("cp.async.commit_group;" ::: "memory")
#define CP_WAIT(n)  asm volatile("cp.async.wait_group %0;" :: "n"(n) : "memory")

__device__ __forceinline__ void ldsm_x4(uint32_t& r0, uint32_t& r1, uint32_t& r2, uint32_t& r3,
                                        uint32_t addr) {
    asm volatile("ldmatrix.sync.aligned.m8n8.x4.shared.b16 {%0,%1,%2,%3}, [%4];"
                 : "=r"(r0), "=r"(r1), "=r"(r2), "=r"(r3) : "r"(addr));
}
__device__ __forceinline__ void ldsm_x2(uint32_t& r0, uint32_t& r1, uint32_t addr) {
    asm volatile("ldmatrix.sync.aligned.m8n8.x2.shared.b16 {%0,%1}, [%2];"
                 : "=r"(r0), "=r"(r1) : "r"(addr));
}
__device__ __forceinline__ void mma16816(float* d, const uint32_t* a, const uint32_t* b) {
    asm volatile("mma.sync.aligned.m16n8k16.row.col.f32.f16.f16.f32 "
                 "{%0,%1,%2,%3}, {%4,%5,%6,%7}, {%8,%9}, {%0,%1,%2,%3};"
                 : "+f"(d[0]), "+f"(d[1]), "+f"(d[2]), "+f"(d[3])
                 : "r"(a[0]), "r"(a[1]), "r"(a[2]), "r"(a[3]), "r"(b[0]), "r"(b[1]));
}

// ===================== problem constants =====================
static constexpr int M_TOTAL = 16384, N_TOTAL = 4096, K_TOTAL = 4096;
static constexpr int BM = 128, BN = 128, BK = 32, STAGES = 4;
static constexpr int KITERS = K_TOTAL / BK;                 // 128
static constexpr uint32_t ROW_B = 80;                       // padded smem row (64B data + 16B pad)
static constexpr uint32_t STAGE_BYTES = 256 * ROW_B;        // A rows 0..127, B rows 128..255
static constexpr uint32_t SMEM_TOTAL = STAGES * STAGE_BYTES; // 81920

// ===================== kernel 0: t12 / t34 =====================
__global__ __launch_bounds__(256) void k_prep(const float* __restrict__ c0,
                                              const float* __restrict__ c1,
                                              const float* __restrict__ c2,
                                              const float* __restrict__ c3) {
    int bid = blockIdx.x;
    if (bid < 1024) {
        int idx = bid * 256 + threadIdx.x;            // (o12, i12, r3)
        int r3 = idx & 63, i12 = (idx >> 6) & 63, o12 = idx >> 12;
        int i1 = i12 >> 3, i2 = i12 & 7, o1 = o12 >> 3, o2 = o12 & 7;
        const float* g1 = c0 + (i1 * 8 + o1) * 64;              // [r2]
        const float* g2 = c1 + (i2 * 8 + o2) * 64 + r3;         // + r2*4096
        float acc = 0.f;
        #pragma unroll 8
        for (int r2 = 0; r2 < 64; ++r2) acc += g1[r2] * g2[r2 * 4096];
        g_t12[(o12 * 64 + i12) * 64 + r3] = acc;
    } else {
        int idx = (bid - 1024) * 256 + threadIdx.x;   // (r3, o34, i34)
        int i34 = idx & 63, o34 = (idx >> 6) & 63, r3 = idx >> 12;
        int i3 = i34 >> 3, i4 = i34 & 7, o3 = o34 >> 3, o4 = o34 & 7;
        const float* g3 = c2 + ((r3 * 8 + i3) * 8 + o3) * 64;   // [r4]
        const float* g4 = c3 + (i4 * 8 + o4);                   // + r4*64
        float acc = 0.f;
        #pragma unroll 8
        for (int r4 = 0; r4 < 64; ++r4) acc += g3[r4] * g4[r4 * 64];
        g_t34[(r3 * 64 + o34) * 64 + i34] = acc;
    }
}

// ===================== kernel 1: build W (fp16) + convert x (fp16) =====================
__global__ __launch_bounds__(256) void k_build(const float* __restrict__ x) {
    __shared__ float sA[64][65];
    __shared__ float sB[64][64];
    if (blockIdx.x < 4096) {
        int o12 = blockIdx.x >> 6, o34 = blockIdx.x & 63;
        int tid = threadIdx.x;
        for (int idx = tid; idx < 4096; idx += 256) {
            sA[idx >> 6][idx & 63] = g_t12[o12 * 4096 + idx];
            sB[idx >> 6][idx & 63] = g_t34[(idx >> 6) * 4096 + o34 * 64 + (idx & 63)];
        }
        __syncthreads();
        int i12 = tid & 63;
        int i34_0 = (tid >> 6) << 4;
        float acc[16];
        #pragma unroll
        for (int j = 0; j < 16; ++j) acc[j] = 0.f;
        #pragma unroll 4
        for (int r = 0; r < 64; ++r) {
            float a = sA[i12][r];
            const float4* bp = reinterpret_cast<const float4*>(&sB[r][i34_0]);
            float4 b0 = bp[0], b1 = bp[1], b2 = bp[2], b3 = bp[3];
            acc[0]  += a * b0.x; acc[1]  += a * b0.y; acc[2]  += a * b0.z; acc[3]  += a * b0.w;
            acc[4]  += a * b1.x; acc[5]  += a * b1.y; acc[6]  += a * b1.z; acc[7]  += a * b1.w;
            acc[8]  += a * b2.x; acc[9]  += a * b2.y; acc[10] += a * b2.z; acc[11] += a * b2.w;
            acc[12] += a * b3.x; acc[13] += a * b3.y; acc[14] += a * b3.z; acc[15] += a * b3.w;
        }
        int n = o12 * 64 + o34;
        __half2* wp = reinterpret_cast<__half2*>(&g_W[(size_t)n * 4096 + i12 * 64 + i34_0]);
        #pragma unroll
        for (int j = 0; j < 8; ++j) wp[j] = __floats2half2_rn(acc[2 * j], acc[2 * j + 1]);
    } else {
        size_t t = (size_t)(blockIdx.x - 4096) * 256 + threadIdx.x;  // 0..16777215
        float4 v = reinterpret_cast<const float4*>(x)[t];
        reinterpret_cast<__half2*>(g_X)[2 * t]     = __floats2half2_rn(v.x, v.y);
        reinterpret_cast<__half2*>(g_X)[2 * t + 1] = __floats2half2_rn(v.z, v.w);
    }
}

// ===================== kernel 2: GEMM (mma.sync fp16, fp32 accum) =====================
__global__ void __launch_bounds__(256, 2) k_gemm(const float* __restrict__ bias,
                                                 float* __restrict__ out) {
    extern __shared__ char smem[];
    const uint32_t sbase = smem_u32(smem);
    const int tid = threadIdx.x, wid = tid >> 5, lid = tid & 31;

    // Grouped tile mapping: 16 M-tiles x 32 N-tiles per group (512 CTAs).
    const int pid = blockIdx.x;
    const int group = pid >> 9;
    const int within = pid & 511;
    const int m0 = (group * 16 + (within & 15)) * BM;
    const int n0 = (within >> 4) * BN;

    const int warp_m = wid >> 2;   // 0..1, 64 rows each
    const int warp_n = wid & 3;    // 0..3, 32 cols each

    // ldmatrix lane-relative offsets within a stage.
    const uint32_t a_lane_off =
        (uint32_t)(warp_m * 64 + (lid & 7) + ((lid >> 3) & 1) * 8) * ROW_B +
        (uint32_t)((lid >> 4) & 1) * 16u;
    const uint32_t b_lane_off =
        (uint32_t)(128 + warp_n * 32 + (lid & 7)) * ROW_B +
        (uint32_t)((lid >> 3) & 1) * 16u;

    const __half* __restrict__ Ag = g_X + (size_t)m0 * K_TOTAL;
    const __half* __restrict__ Bg = g_W + (size_t)n0 * K_TOTAL;

    auto load_stage = [&](int st) {
        const uint32_t sbuf = sbase + (uint32_t)(st & (STAGES - 1)) * STAGE_BYTES;
        const int kk = st * BK;
        #pragma unroll
        for (int it = 0; it < 4; ++it) {
            const int idx = it * 256 + tid;
            const int row = idx >> 2, c = idx & 3;       // row 0..255, 16B chunk 0..3
            const uint32_t sa = sbuf + (uint32_t)row * ROW_B + (uint32_t)c * 16u;
            const __half* g = (row < 128)
                ? (Ag + (size_t)row * K_TOTAL + kk + c * 8)
                : (Bg + (size_t)(row - 128) * K_TOTAL + kk + c * 8);
            cp16(sa, g);
        }
    };

    float acc[4][4][4];
    #pragma unroll
    for (int mt = 0; mt < 4; ++mt)
        #pragma unroll
        for (int nt = 0; nt < 4; ++nt)
            #pragma unroll
            for (int j = 0; j < 4; ++j) acc[mt][nt][j] = 0.f;

    load_stage(0); CP_COMMIT();
    load_stage(1); CP_COMMIT();
    load_stage(2); CP_COMMIT();

    for (int i = 0; i < KITERS; ++i) {
        CP_WAIT(2);
        __syncthreads();
        const uint32_t sbuf = sbase + (uint32_t)(i & (STAGES - 1)) * STAGE_BYTES;

        #pragma unroll
        for (int ks = 0; ks < 2; ++ks) {          // two k16 steps per BK=32 stage
            uint32_t afr[4][4], bfr[4][2];
            #pragma unroll
            for (int mt = 0; mt < 4; ++mt)
                ldsm_x4(afr[mt][0], afr[mt][1], afr[mt][2], afr[mt][3],
                        sbuf + a_lane_off + (uint32_t)mt * (16u * ROW_B) + (uint32_t)ks * 32u);
            #pragma unroll
            for (int nt = 0; nt < 4; ++nt)
                ldsm_x2(bfr[nt][0], bfr[nt][1],
                        sbuf + b_lane_off + (uint32_t)nt * (8u * ROW_B) + (uint32_t)ks * 32u);
            #pragma unroll
            for (int mt = 0; mt < 4; ++mt)
                #pragma unroll
                for (int nt = 0; nt < 4; ++nt)
                    mma16816(acc[mt][nt], afr[mt], bfr[nt]);
        }

        if (i + STAGES - 1 < KITERS) load_stage(i + STAGES - 1);
        CP_COMMIT();                                // empty group in tail keeps counts aligned
    }

    // ===================== epilogue =====================
    const int mbase = m0 + warp_m * 64 + (lid >> 2);
    const int nbase = n0 + warp_n * 32 + (lid & 3) * 2;
    #pragma unroll
    for (int mt = 0; mt < 4; ++mt) {
        const int m = mbase + mt * 16;
        #pragma unroll
        for (int nt = 0; nt < 4; ++nt) {
            const int n = nbase + nt * 8;
            const float2 bv = *reinterpret_cast<const float2*>(bias + n);
            float2 v0 = { acc[mt][nt][0] + bv.x, acc[mt][nt][1] + bv.y };
            float2 v1 = { acc[mt][nt][2] + bv.x, acc[mt][nt][3] + bv.y };
            *reinterpret_cast<float2*>(out + (size_t)m * N_TOTAL + n)       = v0;
            *reinterpret_cast<float2*>(out + (size_t)(m + 8) * N_TOTAL + n) = v1;
        }
    }
}

// ===================== launch =====================
extern "C" void kernel_launch(void* const* d_in, const int* in_sizes, int n_in,
                              void* d_out, int out_size) {
    const float* x    = (const float*)d_in[0];
    const float* c0   = (const float*)d_in[1];
    const float* c1   = (const float*)d_in[2];
    const float* c2   = (const float*)d_in[3];
    const float* c3   = (const float*)d_in[4];
    const float* bias = (const float*)d_in[5];
    float* out = (float*)d_out;

    cudaFuncSetAttribute(k_gemm, cudaFuncAttributeMaxDynamicSharedMemorySize, SMEM_TOTAL);

    k_prep<<<2048, 256>>>(c0, c1, c2, c3);
    k_build<<<4096 + 65536, 256>>>(x);
    k_gemm<<<(M_TOTAL / BM) * (N_TOTAL / BN), 256, SMEM_TOTAL>>>(bias, out);
}

// round 5
// speedup vs baseline: 1.0856x; 1.0856x over previous
#include <cuda_runtime.h>
#include <cuda_fp16.h>
#include <cstdint>

// ===================== device scratch (no allocs allowed) =====================
__device__ float  g_t12[64 * 64 * 64];          // [o12][i12][r3]
__device__ float  g_t34[64 * 64 * 64];          // [r3][o34][i34]
__device__ __half g_W[4096ull * 4096ull];       // [n][k] fp16
__device__ __half g_X[16384ull * 4096ull];      // [m][k] fp16

// ===================== helpers =====================
__device__ __forceinline__ uint32_t smem_u32(const void* p) {
    uint32_t a;
    asm("{ .reg .u64 t; cvta.to.shared.u64 t, %1; cvt.u32.u64 %0, t; }" : "=r"(a) : "l"(p));
    return a;
}
__device__ __forceinline__ void cp16(uint32_t s, const void* g) {
    asm volatile("cp.async.cg.shared.global [%0], [%1], 16;" :: "r"(s), "l"(g));
}
#define CP_COMMIT() asm volatile("cp.async.commit_group;" ::: "memory")
#define CP_WAIT(n)  asm volatile("cp.async.wait_group %0;" :: "n"(n) : "memory")

__device__ __forceinline__ void ldsm_x4(uint32_t& r0, uint32_t& r1, uint32_t& r2, uint32_t& r3,
                                        uint32_t addr) {
    asm volatile("ldmatrix.sync.aligned.m8n8.x4.shared.b16 {%0,%1,%2,%3}, [%4];"
                 : "=r"(r0), "=r"(r1), "=r"(r2), "=r"(r3) : "r"(addr));
}
__device__ __forceinline__ void mma16816(float* d, const uint32_t* a, const uint32_t* b) {
    asm volatile("mma.sync.aligned.m16n8k16.row.col.f32.f16.f16.f32 "
                 "{%0,%1,%2,%3}, {%4,%5,%6,%7}, {%8,%9}, {%0,%1,%2,%3};"
                 : "+f"(d[0]), "+f"(d[1]), "+f"(d[2]), "+f"(d[3])
                 : "r"(a[0]), "r"(a[1]), "r"(a[2]), "r"(a[3]), "r"(b[0]), "r"(b[1]));
}

// ===================== problem constants =====================
static constexpr int M_TOTAL = 16384, N_TOTAL = 4096, K_TOTAL = 4096;
static constexpr int BM = 128, BN = 256, BK = 64, STAGES = 3;
static constexpr int KITERS = K_TOTAL / BK;                  // 64
static constexpr uint32_t ROW_B = 144;                       // 128B data + 16B pad
static constexpr uint32_t STAGE_ROWS = BM + BN;              // 384 (A: 0..127, B: 128..383)
static constexpr uint32_t STAGE_BYTES = STAGE_ROWS * ROW_B;  // 55296
static constexpr uint32_t SMEM_TOTAL = STAGES * STAGE_BYTES; // 165888

// ===================== kernel 0: t12 / t34 =====================
__global__ __launch_bounds__(256) void k_prep(const float* __restrict__ c0,
                                              const float* __restrict__ c1,
                                              const float* __restrict__ c2,
                                              const float* __restrict__ c3) {
    int bid = blockIdx.x;
    if (bid < 1024) {
        int idx = bid * 256 + threadIdx.x;            // (o12, i12, r3)
        int r3 = idx & 63, i12 = (idx >> 6) & 63, o12 = idx >> 12;
        int i1 = i12 >> 3, i2 = i12 & 7, o1 = o12 >> 3, o2 = o12 & 7;
        const float* g1 = c0 + (i1 * 8 + o1) * 64;              // [r2]
        const float* g2 = c1 + (i2 * 8 + o2) * 64 + r3;         // + r2*4096
        float acc = 0.f;
        #pragma unroll 8
        for (int r2 = 0; r2 < 64; ++r2) acc += g1[r2] * g2[r2 * 4096];
        g_t12[(o12 * 64 + i12) * 64 + r3] = acc;
    } else {
        int idx = (bid - 1024) * 256 + threadIdx.x;   // (r3, o34, i34)
        int i34 = idx & 63, o34 = (idx >> 6) & 63, r3 = idx >> 12;
        int i3 = i34 >> 3, i4 = i34 & 7, o3 = o34 >> 3, o4 = o34 & 7;
        const float* g3 = c2 + ((r3 * 8 + i3) * 8 + o3) * 64;   // [r4]
        const float* g4 = c3 + (i4 * 8 + o4);                   // + r4*64
        float acc = 0.f;
        #pragma unroll 8
        for (int r4 = 0; r4 < 64; ++r4) acc += g3[r4] * g4[r4 * 64];
        g_t34[(r3 * 64 + o34) * 64 + i34] = acc;
    }
}

// ===================== kernel 1: build W (fp16) + convert x (fp16) =====================
__global__ __launch_bounds__(256) void k_build(const float* __restrict__ x) {
    __shared__ float sA[64][65];
    __shared__ float sB[64][64];
    if (blockIdx.x < 4096) {
        int o12 = blockIdx.x >> 6, o34 = blockIdx.x & 63;
        int tid = threadIdx.x;
        for (int idx = tid; idx < 4096; idx += 256) {
            sA[idx >> 6][idx & 63] = g_t12[o12 * 4096 + idx];
            sB[idx >> 6][idx & 63] = g_t34[(idx >> 6) * 4096 + o34 * 64 + (idx & 63)];
        }
        __syncthreads();
        int i12 = tid & 63;
        int i34_0 = (tid >> 6) << 4;
        float acc[16];
        #pragma unroll
        for (int j = 0; j < 16; ++j) acc[j] = 0.f;
        #pragma unroll 4
        for (int r = 0; r < 64; ++r) {
            float a = sA[i12][r];
            const float4* bp = reinterpret_cast<const float4*>(&sB[r][i34_0]);
            float4 b0 = bp[0], b1 = bp[1], b2 = bp[2], b3 = bp[3];
            acc[0]  += a * b0.x; acc[1]  += a * b0.y; acc[2]  += a * b0.z; acc[3]  += a * b0.w;
            acc[4]  += a * b1.x; acc[5]  += a * b1.y; acc[6]  += a * b1.z; acc[7]  += a * b1.w;
            acc[8]  += a * b2.x; acc[9]  += a * b2.y; acc[10] += a * b2.z; acc[11] += a * b2.w;
            acc[12] += a * b3.x; acc[13] += a * b3.y; acc[14] += a * b3.z; acc[15] += a * b3.w;
        }
        int n = o12 * 64 + o34;
        __half2* wp = reinterpret_cast<__half2*>(&g_W[(size_t)n * 4096 + i12 * 64 + i34_0]);
        #pragma unroll
        for (int j = 0; j < 8; ++j) wp[j] = __floats2half2_rn(acc[2 * j], acc[2 * j + 1]);
    } else {
        size_t t = (size_t)(blockIdx.x - 4096) * 256 + threadIdx.x;  // 0..16777215
        float4 v = reinterpret_cast<const float4*>(x)[t];
        reinterpret_cast<__half2*>(g_X)[2 * t]     = __floats2half2_rn(v.x, v.y);
        reinterpret_cast<__half2*>(g_X)[2 * t + 1] = __floats2half2_rn(v.z, v.w);
    }
}

// ===================== kernel 2: GEMM 128x256x64, warp tile 64x64 =====================
__global__ void __launch_bounds__(256, 1) k_gemm(const float* __restrict__ bias,
                                                 float* __restrict__ out) {
    extern __shared__ char smem[];
    const uint32_t sbase = smem_u32(smem);
    const int tid = threadIdx.x, wid = tid >> 5, lid = tid & 31;

    // N fastest: 16 n-tiles per m-tile. Wave working set: ~9 A-tiles + full W (32MB) in L2.
    const int m0 = (blockIdx.x >> 4) * BM;
    const int n0 = (blockIdx.x & 15) * BN;

    const int warp_m = wid >> 2;   // 0..1, 64 rows
    const int warp_n = wid & 3;    // 0..3, 64 cols

    // A fragment base: rows warp_m*64 + (lid&7) + ((lid>>3)&1)*8, 16B col = ((lid>>4)&1)*16
    const uint32_t a_lane_off =
        (uint32_t)(warp_m * 64 + (lid & 7) + ((lid >> 3) & 1) * 8) * ROW_B +
        (uint32_t)((lid >> 4) & 1) * 16u;
    // B fragment base (x4 loads 2 n-tiles x 2 k-halves):
    // group g=lid>>3: row = 128 + warp_n*64 + (g>>1)*8 + (lid&7), col = (g&1)*16
    const uint32_t b_lane_off =
        (uint32_t)(128 + warp_n * 64 + (((lid >> 3) >> 1) & 1) * 8 + (lid & 7)) * ROW_B +
        (uint32_t)((lid >> 3) & 1) * 16u;

    const __half* __restrict__ Ag = g_X + (size_t)m0 * K_TOTAL;
    const __half* __restrict__ Bg = g_W + (size_t)n0 * K_TOTAL;

    auto load_stage = [&](int st) {
        const uint32_t sbuf = sbase + (uint32_t)(st % STAGES) * STAGE_BYTES;
        const int kk = st * BK;
        #pragma unroll
        for (int it = 0; it < 12; ++it) {
            const int idx = it * 256 + tid;           // 0..3071
            const int row = idx >> 3, c = idx & 7;    // 384 rows x 8 chunks of 16B
            const uint32_t sa = sbuf + (uint32_t)row * ROW_B + (uint32_t)c * 16u;
            const __half* g = (row < BM)
                ? (Ag + (size_t)row * K_TOTAL + kk + c * 8)
                : (Bg + (size_t)(row - BM) * K_TOTAL + kk + c * 8);
            cp16(sa, g);
        }
    };

    float acc[4][8][4];
    #pragma unroll
    for (int mt = 0; mt < 4; ++mt)
        #pragma unroll
        for (int nt = 0; nt < 8; ++nt)
            #pragma unroll
            for (int j = 0; j < 4; ++j) acc[mt][nt][j] = 0.f;

    load_stage(0); CP_COMMIT();
    load_stage(1); CP_COMMIT();

    for (int i = 0; i < KITERS; ++i) {
        CP_WAIT(1);
        __syncthreads();
        const uint32_t sbuf = sbase + (uint32_t)(i % STAGES) * STAGE_BYTES;

        #pragma unroll
        for (int ks = 0; ks < 4; ++ks) {              // four k16 steps per BK=64
            const uint32_t koff = (uint32_t)ks * 32u;
            uint32_t afr[4][4], bfr[4][4];
            #pragma unroll
            for (int mt = 0; mt < 4; ++mt)
                ldsm_x4(afr[mt][0], afr[mt][1], afr[mt][2], afr[mt][3],
                        sbuf + a_lane_off + (uint32_t)mt * (16u * ROW_B) + koff);
            #pragma unroll
            for (int p = 0; p < 4; ++p)               // p covers n-tiles 2p, 2p+1
                ldsm_x4(bfr[p][0], bfr[p][1], bfr[p][2], bfr[p][3],
                        sbuf + b_lane_off + (uint32_t)p * (16u * ROW_B) + koff);
            #pragma unroll
            for (int mt = 0; mt < 4; ++mt)
                #pragma unroll
                for (int p = 0; p < 4; ++p) {
                    mma16816(acc[mt][2 * p],     afr[mt], &bfr[p][0]);
                    mma16816(acc[mt][2 * p + 1], afr[mt], &bfr[p][2]);
                }
        }

        if (i + STAGES - 1 < KITERS) load_stage(i + STAGES - 1);
        CP_COMMIT();   // empty group in tail keeps wait counts aligned
    }

    // ===================== epilogue =====================
    const int mbase = m0 + warp_m * 64 + (lid >> 2);
    const int nbase = n0 + warp_n * 64 + (lid & 3) * 2;
    #pragma unroll
    for (int mt = 0; mt < 4; ++mt) {
        const int m = mbase + mt * 16;
        #pragma unroll
        for (int nt = 0; nt < 8; ++nt) {
            const int n = nbase + nt * 8;
            const float2 bv = *reinterpret_cast<const float2*>(bias + n);
            float2 v0 = { acc[mt][nt][0] + bv.x, acc[mt][nt][1] + bv.y };
            float2 v1 = { acc[mt][nt][2] + bv.x, acc[mt][nt][3] + bv.y };
            *reinterpret_cast<float2*>(out + (size_t)m * N_TOTAL + n)       = v0;
            *reinterpret_cast<float2*>(out + (size_t)(m + 8) * N_TOTAL + n) = v1;
        }
    }
}

// ===================== launch =====================
extern "C" void kernel_launch(void* const* d_in, const int* in_sizes, int n_in,
                              void* d_out, int out_size) {
    const float* x    = (const float*)d_in[0];
    const float* c0   = (const float*)d_in[1];
    const float* c1   = (const float*)d_in[2];
    const float* c2   = (const float*)d_in[3];
    const float* c3   = (const float*)d_in[4];
    const float* bias = (const float*)d_in[5];
    float* out = (float*)d_out;

    cudaFuncSetAttribute(k_gemm, cudaFuncAttributeMaxDynamicSharedMemorySize, SMEM_TOTAL);

    k_prep<<<2048, 256>>>(c0, c1, c2, c3);
    k_build<<<4096 + 65536, 256>>>(x);
    k_gemm<<<(M_TOTAL / BM) * (N_TOTAL / BN), 256, SMEM_TOTAL>>>(bias, out);
}